// round 4
// baseline (speedup 1.0000x reference)
#include <cuda_runtime.h>

// Problem constants: B=4, H=256, W=256. Torus stencil, mu-subsystem only.
#define BHW     262144
#define HW_MASK 65535
#define W_MASK  255

// Temporal tiling: 32x32 tile, T=10 fused iterations, region 52x52.
#define TILE    32
#define T       10
#define RSIDE   52          // TILE + 2*T
#define RC      2704        // RSIDE*RSIDE
#define RLAST   2652        // RC - RSIDE
#define NTHR    512
#define SLOTS   6           // ceil(RC/NTHR)
#define NLAUNCH 10          // 100 / T

// ---- persistent device state (no allocation allowed) ----
__device__ float  g_mu[2][BHW];   // mu ping-pong (across launches)
__device__ float  g_v [2][BHW];   // momentum ping-pong (halo cells need old v)
__device__ float4 g_c [BHW];      // (ex, ey, eu0, el1)
__device__ float2 g_ac[BHW];      // (2*uw1, uw2*y)

// ---------------- init: pack per-pixel constants ----------------
__global__ __launch_bounds__(256) void init_kernel(const float* __restrict__ y,
                                                   const float2* __restrict__ ew2,
                                                   const float2* __restrict__ un2) {
    const int p = blockIdx.x * 256 + threadIdx.x;
    const int base = p & ~HW_MASK;
    const int i    = p &  HW_MASK;
    const int row  = i & ~W_MASK;
    const int pu = base | ((i + 65280) & HW_MASK);      // (h-1, w)
    const int pl = base | row | ((i + 255) & W_MASK);   // (h, w-1)

    const float yv = y[p];
    const float2 e  = ew2[p];
    const float  eu = ew2[pu].x;
    const float  el = ew2[pl].y;
    const float2 u  = un2[p];

    g_mu[0][p] = yv;
    g_v [0][p] = 0.0f;
    g_c [p]    = make_float4(e.x, e.y, eu, el);
    g_ac[p]    = make_float2(2.0f * u.x, u.y * yv);
}

// ---------------- T fused steps per launch, halo recompute ----------------
__global__ __launch_bounds__(NTHR, 1) void fused_kernel(int s, float* __restrict__ out) {
    __shared__ float sm[2][RC];

    const int tid = threadIdx.x;
    const int blk = blockIdx.x;                  // 256 blocks: 4 imgs x 8x8 tiles
    const int base = (blk >> 6) << 16;           // image base
    const int th = (blk >> 3) & 7;
    const int tw = blk & 7;
    const int h0 = th * TILE - T;                // region origin (wraps via &255)
    const int w0 = tw * TILE - T;

    float4 c4[SLOTS];
    float2 ac2[SLOTS];
    float  vv[SLOTS], mm[SLOTS];
    int    col[SLOTS];

    // Load region state + constants into registers / smem.
    #pragma unroll
    for (int k = 0; k < SLOTS; ++k) {
        const int idx = tid + k * NTHR;
        if (idx < RC) {
            const int r  = idx / RSIDE;
            const int cc = idx - r * RSIDE;
            col[k] = cc;
            const int p = base + (((h0 + r) & 255) << 8) + ((w0 + cc) & 255);
            c4[k]  = g_c[p];
            ac2[k] = g_ac[p];
            vv[k]  = g_v[s][p];
            mm[k]  = g_mu[s][p];
            sm[0][idx] = mm[k];
        }
    }
    __syncthreads();

    // T local iterations; arithmetic order identical to the flat kernel.
    int cur = 0;
    #pragma unroll
    for (int it = 0; it < T; ++it) {
        #pragma unroll
        for (int k = 0; k < SLOTS; ++k) {
            const int idx = tid + k * NTHR;
            if (idx < RC) {
                const int iu = (idx >= RSIDE) ? idx - RSIDE : idx;
                const int id = (idx <  RLAST) ? idx + RSIDE : idx;
                const int il = (col[k] > 0)        ? idx - 1 : idx;
                const int ir = (col[k] < RSIDE-1)  ? idx + 1 : idx;

                float dmu = fmaf(ac2[k].x, mm[k], ac2[k].y);
                dmu = fmaf(c4[k].x, sm[cur][id], dmu);
                dmu = fmaf(c4[k].y, sm[cur][ir], dmu);
                dmu = fmaf(c4[k].z, sm[cur][iu], dmu);
                dmu = fmaf(c4[k].w, sm[cur][il], dmu);

                vv[k] = fmaf(0.7f, vv[k], 0.01f * dmu);
                mm[k] = fminf(fmaxf(mm[k] + vv[k], 0.0f), 63.0f);
                sm[cur ^ 1][idx] = mm[k];
            }
        }
        __syncthreads();
        cur ^= 1;
    }

    // Write back the exact interior tile (distance >= T from region edge).
    #pragma unroll
    for (int k = 0; k < SLOTS; ++k) {
        const int idx = tid + k * NTHR;
        if (idx < RC) {
            const int r  = idx / RSIDE;
            const int cc = col[k];
            if (r >= T && r < T + TILE && cc >= T && cc < T + TILE) {
                const int p = base + (((h0 + r) & 255) << 8) + ((w0 + cc) & 255);
                g_mu[s ^ 1][p] = mm[k];
                g_v [s ^ 1][p] = vv[k];
                if (out) out[p] = mm[k];
            }
        }
    }
}

// ---------------- launch ----------------
extern "C" void kernel_launch(void* const* d_in, const int* in_sizes, int n_in,
                              void* d_out, int out_size) {
    const float* y  = (const float*)d_in[0];
    const float* ew = (const float*)d_in[1];
    const float* un = (const float*)d_in[2];
    float* out = (float*)d_out;

    init_kernel<<<1024, 256>>>(y, (const float2*)ew, (const float2*)un);
    for (int t = 0; t < NLAUNCH; ++t) {
        fused_kernel<<<256, NTHR>>>(t & 1, (t == NLAUNCH - 1) ? out : (float*)nullptr);
    }
}

// round 5
// speedup vs baseline: 1.4803x; 1.4803x over previous
#include <cuda_runtime.h>

// B=4, H=256, W=256 torus. mu-subsystem only (sigma/rou decoupled from output).
// Warp-register stencil: lane = column, 10-row strip per lane in registers.
#define BHW 262144

__device__ float  g_mu[2][BHW];   // mu ping-pong across launches
__device__ float  g_v [2][BHW];   // momentum ping-pong
__device__ float4 g_c [BHW];      // (ex, ey, eu0, el1)
__device__ float2 g_ac[BHW];      // (2*uw1, uw2*y)

// ---------------- init: pack per-pixel constants ----------------
__global__ __launch_bounds__(256) void init_kernel(const float* __restrict__ y,
                                                   const float2* __restrict__ ew2,
                                                   const float2* __restrict__ un2) {
    const int p = blockIdx.x * 256 + threadIdx.x;
    const int base = p & ~65535;
    const int i    = p &  65535;
    const int row  = i & ~255;
    const int pu = base | ((i + 65280) & 65535);
    const int pl = base | row | ((i + 255) & 255);

    const float yv = y[p];
    const float2 e  = ew2[p];
    const float  eu = ew2[pu].x;
    const float  el = ew2[pl].y;
    const float2 u  = un2[p];

    g_mu[0][p] = yv;
    g_v [0][p] = 0.0f;
    g_c [p]    = make_float4(e.x, e.y, eu, el);
    g_ac[p]    = make_float2(2.0f * u.x, u.y * yv);
}

// ---------------- TT fused steps, register-resident strips ----------------
// Block = 8 warps stacked vertically. Region: 80 rows x 32 cols.
// Interior (exact after TT<=8 iters): rows 8..71, cols 8..23 -> 64x16 tile.
template<int TT>
__global__ __launch_bounds__(256, 2) void wreg_kernel(int s, float* __restrict__ out) {
    __shared__ float s_top[2][8][32];   // each band's row-0 mu, double-buffered
    __shared__ float s_bot[2][8][32];   // each band's row-9 mu

    const int lane = threadIdx.x & 31;
    const int w    = threadIdx.x >> 5;          // band 0..7
    const int blk  = blockIdx.x;                // 4 img x 4 vtile x 16 htile
    const int base = (blk >> 6) << 16;
    const int tv   = (blk >> 4) & 3;
    const int th   = blk & 15;
    const int gcol = (th * 16 - 8 + lane) & 255;    // region column (wrapped)
    const int r0   = tv * 64 - 8 + w * 10;          // band's first global row

    float mu[10], v[10], cx[10], cy[10], cz[10], cw[10], ax[10], ay[10];

    #pragma unroll
    for (int r = 0; r < 10; ++r) {
        const int p = base + (((r0 + r) & 255) << 8) + gcol;
        mu[r] = g_mu[s][p];
        v[r]  = g_v[s][p];
        const float4 c = g_c[p];
        cx[r] = c.x; cy[r] = c.y; cz[r] = c.z; cw[r] = c.w;
        const float2 a = g_ac[p];
        ax[r] = a.x; ay[r] = a.y;
    }
    s_top[0][w][lane] = mu[0];
    s_bot[0][w][lane] = mu[9];
    __syncthreads();

    #pragma unroll
    for (int it = 0; it < TT; ++it) {
        const int rb = it & 1;
        // old cross-band boundary values (band edges of region: self = garbage-OK halo)
        float old_above = (w > 0) ? s_bot[rb][w - 1][lane] : mu[0];
        const float dn  = (w < 7) ? s_top[rb][w + 1][lane] : mu[9];

        #pragma unroll
        for (int r = 0; r < 10; ++r) {
            const float cur   = mu[r];
            const float below = (r < 9) ? mu[r + 1] : dn;
            const float left  = __shfl_up_sync(0xFFFFFFFFu, cur, 1);
            const float right = __shfl_down_sync(0xFFFFFFFFu, cur, 1);

            float dmu = fmaf(ax[r], cur, ay[r]);
            dmu = fmaf(cx[r], below, dmu);
            dmu = fmaf(cy[r], right, dmu);
            dmu = fmaf(cz[r], old_above, dmu);
            dmu = fmaf(cw[r], left, dmu);

            v[r]  = fmaf(0.7f, v[r], 0.01f * dmu);
            mu[r] = fminf(fmaxf(cur + v[r], 0.0f), 63.0f);
            old_above = cur;
        }
        s_top[rb ^ 1][w][lane] = mu[0];
        s_bot[rb ^ 1][w][lane] = mu[9];
        __syncthreads();
    }

    // Write back exact interior: region rows 8..71, cols 8..23.
    if (lane >= 8 && lane < 24) {
        #pragma unroll
        for (int r = 0; r < 10; ++r) {
            const int R = w * 10 + r;
            if (R >= 8 && R < 72) {
                const int p = base + (((r0 + r) & 255) << 8) + gcol;
                g_mu[s ^ 1][p] = mu[r];
                g_v [s ^ 1][p] = v[r];
                if (out) out[p] = mu[r];
            }
        }
    }
}

// ---------------- launch: 12 x T8 + 1 x T4 = 100 iterations ----------------
extern "C" void kernel_launch(void* const* d_in, const int* in_sizes, int n_in,
                              void* d_out, int out_size) {
    const float* y  = (const float*)d_in[0];
    const float* ew = (const float*)d_in[1];
    const float* un = (const float*)d_in[2];
    float* out = (float*)d_out;

    init_kernel<<<1024, 256>>>(y, (const float2*)ew, (const float2*)un);
    for (int t = 0; t < 12; ++t)
        wreg_kernel<8><<<256, 256>>>(t & 1, (float*)nullptr);
    wreg_kernel<4><<<256, 256>>>(0, out);
}